// round 1
// baseline (speedup 1.0000x reference)
#include <cuda_runtime.h>
#include <cuda_bf16.h>
#include <cstdint>

// Problem constants
#define BB   128     // batch
#define TT   512     // time steps
#define DIM  256
#define LAT  1024
#define KTOT (DIM + LAT)   // 1280
#define BK   32            // k-tile
#define NKT  (KTOT / BK)   // 40 k-tiles
#define BN   8             // n columns per CTA
#define SA   130           // a_s row stride (padded, even for LDS.64 alignment)

typedef unsigned long long ull;

// Zero buffer for h_{-1} (device globals are zero-initialized at module load)
__device__ float g_zero[BB * LAT];

__device__ __forceinline__ ull fma2(ull a, ull b, ull c) {
    ull d;
    asm("fma.rn.f32x2 %0, %1, %2, %3;" : "=l"(d) : "l"(a), "l"(b), "l"(c));
    return d;
}
__device__ __forceinline__ ull pack2(float w) {
    ull d;
    unsigned u = __float_as_uint(w);
    asm("mov.b64 %0, {%1, %1};" : "=l"(d) : "r"(u));
    return d;
}
__device__ __forceinline__ float2 unp2(ull v) {
    return make_float2(__uint_as_float((unsigned)v),
                       __uint_as_float((unsigned)(v >> 32)));
}

// One recurrence step: out[t] = tanh( [x_t ; h_{t-1}] @ W + b )
// Grid: 128 CTAs (n0 = blockIdx.x*8), 128 threads.
// Per-thread micro-tile: 4 rows (as two f32x2 pairs) x 2 cols.
__global__ void __launch_bounds__(128, 1)
rnn_step(const float* __restrict__ x,
         const float* __restrict__ W,
         const float* __restrict__ b,
         float* __restrict__ out,
         int t)
{
    __shared__ float a_s[2 * BK * SA];     // [buf][k][m], padded
    __shared__ float w_s[2 * BK * BN];     // [buf][k][n]

    const int tid = threadIdx.x;
    const int n0  = blockIdx.x * BN;

    const int tn  = tid & 3;        // n-pair index: cols n0 + 2*tn + {0,1}
    const int tm  = tid >> 2;       // m-group: rows 4*tm .. 4*tm+3
    const int tm4 = tm * 4;

    const float* hp = (t == 0) ? g_zero : out + (size_t)(t - 1) * (BB * LAT);

    // loader mapping (a): thread covers 8 float4s, each (m, k4) with
    // m = i*16 + tid/8, k4 = tid%8  (k = 4*k4 .. 4*k4+3 within the tile)
    const int lm_base = tid >> 3;   // + i*16
    const int lk4     = tid & 7;

    float4 va[8];
    float  wv[2];

    // ---- prefetch tile 0 ----
    {
        const int kt = 0;
#pragma unroll
        for (int i = 0; i < 8; ++i) {
            int m = i * 16 + lm_base;
            const float* p = x + ((size_t)m * TT + t) * DIM + (kt * BK + lk4 * 4);
            va[i] = *(const float4*)p;
        }
#pragma unroll
        for (int i = 0; i < 2; ++i) {
            int k = i * 16 + lm_base;
            int n = tid & 7;
            wv[i] = W[(size_t)(kt * BK + k) * LAT + n0 + n];
        }
    }

    ull acc00 = 0ull, acc01 = 0ull, acc10 = 0ull, acc11 = 0ull;

    for (int kt = 0; kt < NKT; ++kt) {
        const int buf = kt & 1;
        float* as = a_s + buf * (BK * SA);
        float* ws = w_s + buf * (BK * BN);

        // ---- store staged regs into smem (transposed [k][m]) ----
#pragma unroll
        for (int i = 0; i < 8; ++i) {
            int m = i * 16 + lm_base;
            as[(lk4 * 4 + 0) * SA + m] = va[i].x;
            as[(lk4 * 4 + 1) * SA + m] = va[i].y;
            as[(lk4 * 4 + 2) * SA + m] = va[i].z;
            as[(lk4 * 4 + 3) * SA + m] = va[i].w;
        }
#pragma unroll
        for (int i = 0; i < 2; ++i) {
            int k = i * 16 + lm_base;
            int n = tid & 7;
            ws[k * BN + n] = wv[i];
        }
        __syncthreads();

        // ---- prefetch next tile (overlaps compute) ----
        if (kt + 1 < NKT) {
            const int ktn = kt + 1;
            if (ktn < 8) {      // x region (k < 256)
#pragma unroll
                for (int i = 0; i < 8; ++i) {
                    int m = i * 16 + lm_base;
                    const float* p = x + ((size_t)m * TT + t) * DIM + (ktn * BK + lk4 * 4);
                    va[i] = *(const float4*)p;
                }
            } else {            // h region
#pragma unroll
                for (int i = 0; i < 8; ++i) {
                    int m = i * 16 + lm_base;
                    const float* p = hp + (size_t)m * LAT + ((ktn - 8) * BK + lk4 * 4);
                    va[i] = *(const float4*)p;
                }
            }
#pragma unroll
            for (int i = 0; i < 2; ++i) {
                int k = i * 16 + lm_base;
                int n = tid & 7;
                wv[i] = W[(size_t)(ktn * BK + k) * LAT + n0 + n];
            }
        }

        // ---- compute: 32 k-steps, 4 FFMA2 each ----
#pragma unroll
        for (int k = 0; k < BK; ++k) {
            ull a01 = *(const ull*)(as + k * SA + tm4);
            ull a23 = *(const ull*)(as + k * SA + tm4 + 2);
            float w0 = ws[k * BN + 2 * tn];
            float w1 = ws[k * BN + 2 * tn + 1];
            ull w00 = pack2(w0);
            ull w11 = pack2(w1);
            acc00 = fma2(a01, w00, acc00);
            acc01 = fma2(a01, w11, acc01);
            acc10 = fma2(a23, w00, acc10);
            acc11 = fma2(a23, w11, acc11);
        }
        __syncthreads();
    }

    // ---- epilogue: bias + tanh + store ----
    const int nb = n0 + 2 * tn;
    const float b0 = b[nb];
    const float b1 = b[nb + 1];

    float2 r0 = unp2(acc00);   // rows tm4, tm4+1 @ col nb
    float2 r1 = unp2(acc01);   // rows tm4, tm4+1 @ col nb+1
    float2 r2 = unp2(acc10);   // rows tm4+2, tm4+3 @ col nb
    float2 r3 = unp2(acc11);   // rows tm4+2, tm4+3 @ col nb+1

    float* o = out + ((size_t)t * BB + tm4) * LAT + nb;
    o[0]            = tanhf(r0.x + b0);
    o[1]            = tanhf(r1.x + b1);
    o[LAT + 0]      = tanhf(r0.y + b0);
    o[LAT + 1]      = tanhf(r1.y + b1);
    o[2 * LAT + 0]  = tanhf(r2.x + b0);
    o[2 * LAT + 1]  = tanhf(r3.x + b1);
    o[3 * LAT + 0]  = tanhf(r2.y + b0);
    o[3 * LAT + 1]  = tanhf(r3.y + b1);
}

extern "C" void kernel_launch(void* const* d_in, const int* in_sizes, int n_in,
                              void* d_out, int out_size)
{
    const float* x = (const float*)d_in[0];   // (128, 512, 256) f32
    const float* W = (const float*)d_in[1];   // (1280, 1024) f32
    const float* b = (const float*)d_in[2];   // (1024,) f32
    float* out = (float*)d_out;               // (512, 128, 1024) f32

    dim3 grid(LAT / BN);   // 128 CTAs
    dim3 block(128);
    for (int t = 0; t < TT; ++t) {
        rnn_step<<<grid, block>>>(x, W, b, out, t);
    }
}

// round 3
// speedup vs baseline: 1.2923x; 1.2923x over previous
#include <cuda_runtime.h>
#include <cstdint>

#define TT   512
#define BB   128
#define LATN 1024
#define DIMX 256
#define BM   64
#define BN   16
#define BK   64
#define SAR  68      // a-tile row stride [m][k] (16B-aligned rows)
#define SAW  66      // w-tile row stride [n][k]
#define NT   256

typedef unsigned long long ull;

// publish counters: [mi][sub(128-col chunk)][pad to 128B]
__device__ unsigned g_cnt[2][8][32];

__device__ __forceinline__ ull fma2(ull a, ull b, ull c) {
    ull d; asm("fma.rn.f32x2 %0, %1, %2, %3;" : "=l"(d) : "l"(a), "l"(b), "l"(c)); return d;
}
__device__ __forceinline__ ull add2(ull a, ull b) {
    ull d; asm("add.rn.f32x2 %0, %1, %2;" : "=l"(d) : "l"(a), "l"(b)); return d;
}
__device__ __forceinline__ float2 unp2(ull v) {
    float2 f; asm("mov.b64 {%0, %1}, %2;" : "=f"(f.x), "=f"(f.y) : "l"(v)); return f;
}

__global__ void __launch_bounds__(NT, 1)
rnn_persist(const float* __restrict__ x, const float* __restrict__ W,
            const float* __restrict__ b, float* __restrict__ out)
{
    __shared__ float sA[2][BM * SAR];   // a-tile [m][k], 2 bufs  (34816 B)
    __shared__ float sWt[2][BN * SAW];  // w-tile [n][k], 2 bufs  ( 8448 B)

    const int tid = threadIdx.x;
    const int cta = blockIdx.x;
    const int mi  = cta & 1;            // M-half
    const int nj  = cta >> 1;           // N-tile 0..63
    const int m0  = mi * BM;
    const int n0  = nj * BN;
    const int sub = nj >> 3;            // 128-col chunk this CTA produces

    const int z    = tid >> 7;          // k-split half of each tile
    const int t128 = tid & 127;
    const int tn   = t128 & 7;          // col pair: n0 + 2tn + {0,1}
    const int tm   = t128 >> 3;         // row quad: 4tm .. 4tm+3

    const int lk4 = tid & 7;            // loader: k-quad {lk4, lk4+8}
    const int lm  = tid >> 3;           // loader: rows {lm, lm+32}

    const int wk = tid >> 2;            // w loader: k row 0..63
    const int wc = tid & 3;             // w loader: col quad

    const float b0 = b[n0 + 2 * tn];
    const float b1 = b[n0 + 2 * tn + 1];

    long long budget = 1LL << 22;       // bounded spins: hang -> wrong answer, not timeout

    float4 va0, va1, va2, va3, wv;

#define LDG_TILE(kt_, t_)                                                   \
  { const int _kt = (kt_);                                                  \
    const float* _q = W + (size_t)(_kt * BK + wk) * LATN + n0 + 4 * wc;     \
    wv = *(const float4*)_q;                                                \
    if (_kt < 4) {                                                          \
      const float* _p = x + (size_t)(m0 + lm) * (TT * DIMX)                 \
                          + (size_t)(t_) * DIMX + _kt * BK + 4 * lk4;       \
      va0 = *(const float4*)(_p);                                           \
      va1 = *(const float4*)(_p + 32);                                      \
      va2 = *(const float4*)(_p + 32 * (TT * DIMX));                        \
      va3 = *(const float4*)(_p + 32 * (TT * DIMX) + 32);                   \
    } else {                                                                \
      const float* _p = out + (size_t)((t_) - 1) * (BB * LATN)              \
                            + (size_t)(m0 + lm) * LATN                      \
                            + (_kt * BK - DIMX) + 4 * lk4;                  \
      va0 = *(const float4*)(_p);                                           \
      va1 = *(const float4*)(_p + 32);                                      \
      va2 = *(const float4*)(_p + 32 * LATN);                               \
      va3 = *(const float4*)(_p + 32 * LATN + 32);                          \
    } }

#define STS_TILE(buf_)                                                      \
  { float* _a = &sA[buf_][0];                                               \
    *(float4*)(_a + lm * SAR + 4 * lk4)            = va0;                   \
    *(float4*)(_a + lm * SAR + 4 * lk4 + 32)       = va1;                   \
    *(float4*)(_a + (lm + 32) * SAR + 4 * lk4)     = va2;                   \
    *(float4*)(_a + (lm + 32) * SAR + 4 * lk4 + 32) = va3;                  \
    float* _w = &sWt[buf_][0];                                              \
    _w[(4 * wc + 0) * SAW + wk] = wv.x;                                     \
    _w[(4 * wc + 1) * SAW + wk] = wv.y;                                     \
    _w[(4 * wc + 2) * SAW + wk] = wv.z;                                     \
    _w[(4 * wc + 3) * SAW + wk] = wv.w;                                     \
  }

    // k-pair accumulation: each acc ull holds (sum over even k, sum over odd k)
#define COMPUTE_TILE(buf_)                                                  \
  { const float* _a = &sA[buf_][4 * tm * SAR + z * 32];                     \
    const float* _w = &sWt[buf_][2 * tn * SAW + z * 32];                    \
    _Pragma("unroll")                                                       \
    for (int kp = 0; kp < 16; ++kp) {                                       \
      ull A0 = *(const ull*)(_a + 2 * kp);                                  \
      ull A1 = *(const ull*)(_a + SAR + 2 * kp);                            \
      ull A2 = *(const ull*)(_a + 2 * SAR + 2 * kp);                        \
      ull A3 = *(const ull*)(_a + 3 * SAR + 2 * kp);                        \
      ull W0 = *(const ull*)(_w + 2 * kp);                                  \
      ull W1 = *(const ull*)(_w + SAW + 2 * kp);                            \
      ac00 = fma2(A0, W0, ac00);  ac01 = fma2(A0, W1, ac01);                \
      ac10 = fma2(A1, W0, ac10);  ac11 = fma2(A1, W1, ac11);                \
      ac20 = fma2(A2, W0, ac20);  ac21 = fma2(A2, W1, ac21);                \
      ac30 = fma2(A3, W0, ac30);  ac31 = fma2(A3, W1, ac31);                \
    } }

#define WAIT_SUB(s_, tgt_)                                                  \
  { if (tid == 0) {                                                         \
      const unsigned* _c = &g_cnt[mi][s_][0];                               \
      unsigned _v;                                                          \
      for (;;) {                                                            \
        asm volatile("ld.acquire.gpu.u32 %0, [%1];" : "=r"(_v) : "l"(_c));  \
        if (_v >= (unsigned)(tgt_) || budget <= 0) break;                   \
        __nanosleep(64); --budget;                                          \
      }                                                                     \
    }                                                                       \
    __syncthreads(); }

#pragma unroll 1
    for (int t = 0; t < TT; ++t) {
        ull ac00 = 0, ac01 = 0, ac10 = 0, ac11 = 0;
        ull ac20 = 0, ac21 = 0, ac30 = 0, ac31 = 0;

        const int ntiles = (t == 0) ? 4 : 20;   // x tiles 0..3, h tiles 4..19

        LDG_TILE(0, t);
#pragma unroll 1
        for (int kt = 0; kt < ntiles; ++kt) {
            STS_TILE(kt & 1);
            __syncthreads();
            if (kt + 1 < ntiles) {
                if (kt + 1 >= 4 && (((kt + 1) - 4) & 1) == 0)
                    WAIT_SUB(((kt + 1) - 4) >> 1, t * 8);
                LDG_TILE(kt + 1, t);
            }
            COMPUTE_TILE(kt & 1);
        }

        // ---- reduce the two z-halves via smem scratch (buf 0; last tile used buf 1) ----
        ull* red = (ull*)&sA[0][0];
        __syncthreads();
        if (z == 1) {
            red[t128 * 8 + 0] = ac00;  red[t128 * 8 + 1] = ac01;
            red[t128 * 8 + 2] = ac10;  red[t128 * 8 + 3] = ac11;
            red[t128 * 8 + 4] = ac20;  red[t128 * 8 + 5] = ac21;
            red[t128 * 8 + 6] = ac30;  red[t128 * 8 + 7] = ac31;
        }
        __syncthreads();
        if (z == 0) {
            ac00 = add2(ac00, red[t128 * 8 + 0]);  ac01 = add2(ac01, red[t128 * 8 + 1]);
            ac10 = add2(ac10, red[t128 * 8 + 2]);  ac11 = add2(ac11, red[t128 * 8 + 3]);
            ac20 = add2(ac20, red[t128 * 8 + 4]);  ac21 = add2(ac21, red[t128 * 8 + 5]);
            ac30 = add2(ac30, red[t128 * 8 + 6]);  ac31 = add2(ac31, red[t128 * 8 + 7]);

            float2 r;
            float* o = out + (size_t)t * (BB * LATN)
                           + (size_t)(m0 + 4 * tm) * LATN + n0 + 2 * tn;
            r = unp2(ac00); float v00 = r.x + r.y + b0;
            r = unp2(ac01); float v01 = r.x + r.y + b1;
            r = unp2(ac10); float v10 = r.x + r.y + b0;
            r = unp2(ac11); float v11 = r.x + r.y + b1;
            r = unp2(ac20); float v20 = r.x + r.y + b0;
            r = unp2(ac21); float v21 = r.x + r.y + b1;
            r = unp2(ac30); float v30 = r.x + r.y + b0;
            r = unp2(ac31); float v31 = r.x + r.y + b1;
            *(float2*)(o)            = make_float2(tanhf(v00), tanhf(v01));
            *(float2*)(o + LATN)     = make_float2(tanhf(v10), tanhf(v11));
            *(float2*)(o + 2 * LATN) = make_float2(tanhf(v20), tanhf(v21));
            *(float2*)(o + 3 * LATN) = make_float2(tanhf(v30), tanhf(v31));
        }

        // ---- publish h_t ----
        __threadfence();
        __syncthreads();
        if (tid == 0) atomicAdd(&g_cnt[mi][sub][0], 1u);
    }

    // ---- reset counters for the next launch (one resetter per counter) ----
    if (tid == 0 && (nj & 7) == 0) {
        unsigned* c_ = &g_cnt[mi][sub][0];
        unsigned v_;
        for (;;) {
            asm volatile("ld.acquire.gpu.u32 %0, [%1];" : "=r"(v_) : "l"(c_));
            if (v_ >= (unsigned)(TT * 8) || budget <= 0) break;
            __nanosleep(64); --budget;
        }
        asm volatile("st.relaxed.gpu.u32 [%0], %1;" :: "l"(c_), "r"(0u) : "memory");
    }
}

extern "C" void kernel_launch(void* const* d_in, const int* in_sizes, int n_in,
                              void* d_out, int out_size)
{
    const float* x = (const float*)d_in[0];   // (128, 512, 256) f32
    const float* W = (const float*)d_in[1];   // (1280, 1024) f32
    const float* b = (const float*)d_in[2];   // (1024,) f32
    float* out = (float*)d_out;               // (512, 128, 1024) f32

    rnn_persist<<<128, NT>>>(x, W, b, out);
}